// round 4
// baseline (speedup 1.0000x reference)
#include <cuda_runtime.h>
#include <cuda_bf16.h>

// LNN Euler-Lagrange residual: ReLU MLP => grad-of-grad vanishes; output is
// exactly -dL/dq (forward for masks + one backward).
//
// Round-4: f32x2 packing over the HIDDEN dimension. Weight pairs are
// contiguous in smem, so one LDS.128 feeds two fma.rn.f32x2 with no
// duplication movs. Pass orientations chosen so register arrays are only
// indexed by compile-time constants. Persistent blocks amortize staging.

typedef unsigned long long u64;

__device__ __forceinline__ u64 pack2(float lo, float hi) {
    u64 d; asm("mov.b64 %0, {%1, %2};" : "=l"(d) : "f"(lo), "f"(hi)); return d;
}
__device__ __forceinline__ void unpack2(u64 v, float& lo, float& hi) {
    asm("mov.b64 {%0, %1}, %2;" : "=f"(lo), "=f"(hi) : "l"(v));
}
__device__ __forceinline__ u64 fma2(u64 a, u64 b, u64 c) {
    u64 d; asm("fma.rn.f32x2 %0, %1, %2, %3;" : "=l"(d) : "l"(a), "l"(b), "l"(c)); return d;
}
__device__ __forceinline__ u64 add2(u64 a, u64 b) {
    u64 d; asm("add.rn.f32x2 %0, %1, %2;" : "=l"(d) : "l"(a), "l"(b)); return d;
}

__global__ void __launch_bounds__(128, 4)
lnn_kernel(const float* __restrict__ X,
           const float* __restrict__ W1g, const float* __restrict__ b1g,
           const float* __restrict__ W2g, const float* __restrict__ b2g,
           const float* __restrict__ W3g,
           float* __restrict__ out, int B)
{
    __shared__ float sW1[4096];    // row i = W1[i,:]  (L1 accumulate; out dots)
    __shared__ float sW2T[4096];   // row j = W2[:,j]  (L2 sign dots; t accumulate)
    __shared__ float sb1[64], sb2[64], sW3[64];

    const int t = threadIdx.x;
    // Staging. sW2T stored transposed with conflict-free STS (consecutive
    // threads write consecutive addresses); the strided LDG is L1-absorbed
    // and amortized by persistence.
    for (int i = t; i < 4096; i += 128) {
        sW1[i] = W1g[i];
        const int c = i >> 6, r = i & 63;
        sW2T[c * 64 + r] = W2g[r * 64 + c];
    }
    if (t < 64) { sb1[t] = b1g[t]; sb2[t] = b2g[t]; sW3[t] = W3g[t]; }
    __syncthreads();

    const int stride = gridDim.x * 128;
    for (int s = blockIdx.x * 128 + t; s < B; s += stride) {

        // ================= layer 1: h = relu(x @ W1 + b1) ==================
        u64 h[32];
        {
            const u64* bp = reinterpret_cast<const u64*>(sb1);
            #pragma unroll
            for (int p = 0; p < 32; p++) h[p] = bp[p];
        }
        const float4* xg = reinterpret_cast<const float4*>(X + (size_t)s * 64);
        #pragma unroll 1
        for (int i4 = 0; i4 < 16; i4++) {
            const float4 xv = xg[i4];
            const ulonglong2* row =
                reinterpret_cast<const ulonglong2*>(sW1 + i4 * 256);
            const u64 x0 = pack2(xv.x, xv.x), x1 = pack2(xv.y, xv.y),
                      x2 = pack2(xv.z, xv.z), x3 = pack2(xv.w, xv.w);
            #pragma unroll
            for (int e = 0; e < 16; e++) {
                ulonglong2 w;
                w = row[e];
                h[2*e]   = fma2(x0, w.x, h[2*e]);
                h[2*e+1] = fma2(x0, w.y, h[2*e+1]);
                w = row[16 + e];
                h[2*e]   = fma2(x1, w.x, h[2*e]);
                h[2*e+1] = fma2(x1, w.y, h[2*e+1]);
                w = row[32 + e];
                h[2*e]   = fma2(x2, w.x, h[2*e]);
                h[2*e+1] = fma2(x2, w.y, h[2*e+1]);
                w = row[48 + e];
                h[2*e]   = fma2(x3, w.x, h[2*e]);
                h[2*e+1] = fma2(x3, w.y, h[2*e+1]);
            }
        }

        // relu + layer-1 mask (bit j = h_j > 0)
        u64 m1 = 0ull;
        #pragma unroll
        for (int p = 0; p < 32; p++) {
            float lo, hi; unpack2(h[p], lo, hi);
            lo = fmaxf(lo, 0.0f); hi = fmaxf(hi, 0.0f);
            if (lo > 0.0f) m1 |= 1ull << (2*p);
            if (hi > 0.0f) m1 |= 1ull << (2*p + 1);
            h[p] = pack2(lo, hi);
        }

        // ============= layer 2: only sign(h @ W2 + b2) needed ==============
        u64 m2 = 0ull;
        #pragma unroll 2
        for (int j = 0; j < 64; j++) {
            const ulonglong2* row =
                reinterpret_cast<const ulonglong2*>(sW2T + j * 64);
            u64 a0 = 0ull, a1 = 0ull, a2 = 0ull, a3 = 0ull;
            #pragma unroll
            for (int e = 0; e < 8; e++) {
                ulonglong2 w0 = row[2*e], w1 = row[2*e + 1];
                a0 = fma2(h[4*e+0], w0.x, a0);
                a1 = fma2(h[4*e+1], w0.y, a1);
                a2 = fma2(h[4*e+2], w1.x, a2);
                a3 = fma2(h[4*e+3], w1.y, a3);
            }
            float lo, hi; unpack2(add2(add2(a0, a1), add2(a2, a3)), lo, hi);
            if ((lo + hi) + sb2[j] > 0.0f) m2 |= 1ull << j;
        }

        // ====== t = W2 @ d2, where d2_j = (m2_j ? W3_j : 0); h is dead =====
        u64 tv[32];
        #pragma unroll
        for (int p = 0; p < 32; p++) tv[p] = 0ull;
        #pragma unroll 1
        for (int j = 0; j < 64; j++) {
            const float d = ((m2 >> j) & 1ull) ? sW3[j] : 0.0f;
            const u64 dp = pack2(d, d);
            const ulonglong2* row =
                reinterpret_cast<const ulonglong2*>(sW2T + j * 64);
            #pragma unroll
            for (int e = 0; e < 16; e++) {
                ulonglong2 w = row[e];
                tv[2*e]   = fma2(dp, w.x, tv[2*e]);
                tv[2*e+1] = fma2(dp, w.y, tv[2*e+1]);
            }
        }

        // gate by layer-1 mask (output negation folded into final hsum)
        #pragma unroll
        for (int p = 0; p < 32; p++) {
            float lo, hi; unpack2(tv[p], lo, hi);
            lo = ((m1 >> (2*p))     & 1ull) ? lo : 0.0f;
            hi = ((m1 >> (2*p + 1)) & 1ull) ? hi : 0.0f;
            tv[p] = pack2(lo, hi);
        }

        // ========== out_i = -(W1[i,:] . tgated), i < 32 (q rows) ===========
        float* og = out + (size_t)s * 32;
        #pragma unroll 1
        for (int i = 0; i < 32; i += 4) {
            const ulonglong2* rA =
                reinterpret_cast<const ulonglong2*>(sW1 + i * 64);
            u64 acc[8];
            #pragma unroll
            for (int q = 0; q < 8; q++) acc[q] = 0ull;
            #pragma unroll
            for (int e = 0; e < 16; e++) {
                #pragma unroll
                for (int rr = 0; rr < 4; rr++) {
                    ulonglong2 w = rA[rr * 16 + e];
                    acc[2*rr]   = fma2(tv[2*e],   w.x, acc[2*rr]);
                    acc[2*rr+1] = fma2(tv[2*e+1], w.y, acc[2*rr+1]);
                }
            }
            float4 res;
            {
                float lo, hi;
                unpack2(add2(acc[0], acc[1]), lo, hi); res.x = -(lo + hi);
                unpack2(add2(acc[2], acc[3]), lo, hi); res.y = -(lo + hi);
                unpack2(add2(acc[4], acc[5]), lo, hi); res.z = -(lo + hi);
                unpack2(add2(acc[6], acc[7]), lo, hi); res.w = -(lo + hi);
            }
            reinterpret_cast<float4*>(og)[i >> 2] = res;
        }
    }
}

extern "C" void kernel_launch(void* const* d_in, const int* in_sizes, int n_in,
                              void* d_out, int out_size)
{
    const float* X  = (const float*)d_in[0];
    const float* W1 = (const float*)d_in[1];
    const float* b1 = (const float*)d_in[2];
    const float* W2 = (const float*)d_in[3];
    const float* b2 = (const float*)d_in[4];
    const float* W3 = (const float*)d_in[5];
    float* out = (float*)d_out;

    const int B = in_sizes[0] / 64;
    int grid = 148 * 4;                       // persistent: 4 blocks/SM
    const int maxg = (B + 127) / 128;
    if (grid > maxg) grid = maxg;
    lnn_kernel<<<grid, 128>>>(X, W1, b1, W2, b2, W3, out, B);
}